// round 11
// baseline (speedup 1.0000x reference)
#include <cuda_runtime.h>
#include <cstdint>

// ---------------- static scratch (no allocs allowed) ----------------
__device__ float g_xg[32768 * 3072];        // input-projection buffer (max 3H=3072)
__device__ float g_actB[32768 * 1024];      // raw GRU outputs (pre-LN)
__device__ unsigned g_h[2][64 * 1024];      // double-buffered hidden state (tf32 bits)
__device__ float g_psum[128 * 32768];       // per-CTA partial row sums
__device__ float g_psqs[128 * 32768];       // per-CTA partial row sumsq
__device__ float g_sum[32768];              // reduced row sums
__device__ float g_sqs[32768];              // reduced row sumsq
__device__ unsigned g_arr[128 * 32];        // per-CTA progress flags (128B stride)

// ---------------- helpers ----------------
__device__ __forceinline__ unsigned f2tf(float x) {
    unsigned r; asm("cvt.rna.tf32.f32 %0, %1;" : "=r"(r) : "f"(x)); return r;
}
__device__ __forceinline__ void mma8(float* c, const unsigned* a, const unsigned* b) {
    asm volatile("mma.sync.aligned.m16n8k8.row.col.f32.tf32.tf32.f32 "
                 "{%0,%1,%2,%3}, {%4,%5,%6,%7}, {%8,%9}, {%0,%1,%2,%3};"
                 : "+f"(c[0]), "+f"(c[1]), "+f"(c[2]), "+f"(c[3])
                 : "r"(a[0]), "r"(a[1]), "r"(a[2]), "r"(a[3]),
                   "r"(b[0]), "r"(b[1]));
}
__device__ __forceinline__ unsigned flag_acq(const unsigned* p) {
    unsigned v;
    asm volatile("ld.acquire.gpu.u32 %0, [%1];" : "=r"(v) : "l"(p) : "memory");
    return v;
}

// ---------------- input-projection GEMM with optional fused LN ----------------
template<int K, bool LN>
__global__ void __launch_bounds__(256) gemm_xg(const float* __restrict__ A,
                                               const float* __restrict__ W,
                                               int N,
                                               const float* __restrict__ gma,
                                               const float* __restrict__ bta,
                                               int nprev) {
    __shared__ unsigned As[128 * 36];
    __shared__ unsigned Bs[64 * 36];
    __shared__ float gS[K], bS[K];
    __shared__ float rmS[128], rsS[128];

    const int m0 = blockIdx.y * 128;
    const int n0 = blockIdx.x * 64;
    const int tid = threadIdx.x;
    const int lane = tid & 31, wid = tid >> 5;
    const int wm = (wid & 3) * 32, wn = (wid >> 2) * 32;

    if (blockIdx.x == 0 && blockIdx.y == 0 && tid < 128)
        g_arr[tid * 32] = 0u;              // reset progress flags for the next rec

    if (LN) {
        for (int i = tid; i < K; i += 256) { gS[i] = gma[i]; bS[i] = bta[i]; }
        if (tid < 128) {
            int m = m0 + tid;
            float s, q;
            if ((m & 511) >= 510) {
                s = 0.f; q = 0.f;
                for (int c = 0; c < nprev; c++) {
                    s += g_psum[(size_t)c * 32768 + m];
                    q += g_psqs[(size_t)c * 32768 + m];
                }
            } else {
                s = g_sum[m]; q = g_sqs[m];
            }
            float mean = s * (1.f / K);
            float var = q * (1.f / K) - mean * mean;
            rmS[tid] = mean;
            rsS[tid] = rsqrtf(var);
        }
        __syncthreads();
    }

    float acc[2][4][4];
#pragma unroll
    for (int i = 0; i < 2; i++)
#pragma unroll
        for (int j = 0; j < 4; j++)
#pragma unroll
            for (int k = 0; k < 4; k++) acc[i][j][k] = 0.f;

    const int lr = tid >> 3;
    const int lc = (tid & 7) * 4;

    for (int kc = 0; kc < K; kc += 32) {
#pragma unroll
        for (int i = 0; i < 4; i++) {
            int r = lr + i * 32;
            float4 v = *reinterpret_cast<const float4*>(&A[(size_t)(m0 + r) * K + kc + lc]);
            if (LN) {
                float mm = rmS[r], ss = rsS[r];
                int k = kc + lc;
                v.x = (v.x - mm) * ss * gS[k]     + bS[k];
                v.y = (v.y - mm) * ss * gS[k + 1] + bS[k + 1];
                v.z = (v.z - mm) * ss * gS[k + 2] + bS[k + 2];
                v.w = (v.w - mm) * ss * gS[k + 3] + bS[k + 3];
            }
            *reinterpret_cast<uint4*>(&As[r * 36 + lc]) =
                make_uint4(f2tf(v.x), f2tf(v.y), f2tf(v.z), f2tf(v.w));
        }
#pragma unroll
        for (int i = 0; i < 2; i++) {
            int r = lr + i * 32;
            float4 v = *reinterpret_cast<const float4*>(&W[(size_t)(n0 + r) * K + kc + lc]);
            *reinterpret_cast<uint4*>(&Bs[r * 36 + lc]) =
                make_uint4(f2tf(v.x), f2tf(v.y), f2tf(v.z), f2tf(v.w));
        }
        __syncthreads();
#pragma unroll
        for (int k8 = 0; k8 < 4; k8++) {
            const int kb = k8 * 8;
            unsigned a[2][4], b[4][2];
#pragma unroll
            for (int mf = 0; mf < 2; mf++) {
                int rb = wm + mf * 16 + (lane >> 2);
                a[mf][0] = As[rb * 36 + kb + (lane & 3)];
                a[mf][1] = As[(rb + 8) * 36 + kb + (lane & 3)];
                a[mf][2] = As[rb * 36 + kb + (lane & 3) + 4];
                a[mf][3] = As[(rb + 8) * 36 + kb + (lane & 3) + 4];
            }
#pragma unroll
            for (int nf = 0; nf < 4; nf++) {
                int cb = wn + nf * 8 + (lane >> 2);
                b[nf][0] = Bs[cb * 36 + kb + (lane & 3)];
                b[nf][1] = Bs[cb * 36 + kb + (lane & 3) + 4];
            }
#pragma unroll
            for (int mf = 0; mf < 2; mf++)
#pragma unroll
                for (int nf = 0; nf < 4; nf++)
                    mma8(acc[mf][nf], a[mf], b[nf]);
        }
        __syncthreads();
    }
#pragma unroll
    for (int mf = 0; mf < 2; mf++)
#pragma unroll
        for (int nf = 0; nf < 4; nf++) {
            int row = m0 + wm + mf * 16 + (lane >> 2);
            int col = n0 + wn + nf * 8 + 2 * (lane & 3);
            g_xg[(size_t)row * N + col]     = acc[mf][nf][0];
            g_xg[(size_t)row * N + col + 1] = acc[mf][nf][1];
            g_xg[(size_t)(row + 8) * N + col]     = acc[mf][nf][2];
            g_xg[(size_t)(row + 8) * N + col + 1] = acc[mf][nf][3];
        }
}

// ---------------- persistent GRU recurrence (flag-pipelined, no grid barrier) ----------------
// grid = H/8 CTAs, 256 threads, 8 warps: warp (mi = wid&1, kq = wid>>1).
// Per-CTA progress flag published once per step (release). Consumers speculatively
// issue flag acquire + h prefetch for chunk ch+1 BEFORE mma(ch), validate after:
// fast path has zero added stall; slow path spins + reloads. 4 producer CTAs per
// warp per chunk (ch*16 + kq*4 + 0..3). h double-buffered (publish(t+1) implies
// all buffer[t&1] reads done). LN shadow: warp 7 reduces step t-2 at loop top.
template<int H>
__global__ void __launch_bounds__(256, 1) gru_rec(const float* __restrict__ Whh) {
    constexpr int NCH = H / 128;         // 128-wide chunks; NCH*16 == NC
    constexpr int NC  = H / 8;           // == gridDim.x  (<= 128)
    extern __shared__ unsigned char smem_raw[];
    unsigned* Wf = reinterpret_cast<unsigned*>(smem_raw);      // [H/8][3][64] packed B
    unsigned* Apriv = Wf + (H / 8) * 192;                      // 8 warps x 2 x [32][36]
    float* hgS = reinterpret_cast<float*>(Apriv + 8 * 2 * 1152); // 4 x [64][40]

    const float* xg = g_xg;
    float* y = g_actB;
    const int tid = threadIdx.x;
    const int lane = tid & 31, wid = tid >> 5;
    const int cta = blockIdx.x;
    const int c0 = cta * 8;
    const int q = lane >> 2, r4 = lane & 3;
    const int mi = wid & 1;              // m-half: rows mi*32..mi*32+31
    const int kq = wid >> 1;             // k-quarter within each 128-chunk

    // one-time: Whh slice -> SMEM in fragment-packed tf32 order
    {
        constexpr int nf4 = H / 4;
        for (int idx = tid; idx < 24 * nf4; idx += 256) {
            int nn = idx / nf4;               // 0..23 : gate*8 + j
            int c4 = (idx % nf4) * 4;         // k, multiple of 4
            int gate = nn >> 3, j = nn & 7;
            float4 v = *reinterpret_cast<const float4*>(&Whh[(size_t)(gate * H + c0 + j) * H + c4]);
            int kb8 = c4 >> 3;
            int half = (c4 >> 2) & 1;
            unsigned* base = Wf + (kb8 * 3 + gate) * 64 + j * 8 + half;
            base[0] = f2tf(v.x); base[2] = f2tf(v.y);
            base[4] = f2tf(v.z); base[6] = f2tf(v.w);
        }
    }
    __syncthreads();

    const int col = tid & 7;             // epilogue: own column
    const int brow = tid >> 3;           // epilogue: batch rows brow, brow+32
    float hl[2] = {0.f, 0.f};
    float pxr[2], pxz[2], pxn[2];

#define PF_XG(TT) do { \
        _Pragma("unroll") \
        for (int it = 0; it < 2; it++) { \
            int b_ = brow + it * 32; \
            const float* xrow = xg + ((size_t)b_ * 512 + (TT)) * (size_t)(3 * H); \
            pxr[it] = __ldcs(xrow + c0 + col); \
            pxz[it] = __ldcs(xrow + H + c0 + col); \
            pxn[it] = __ldcs(xrow + 2 * H + c0 + col); \
        } } while (0)

    PF_XG(0);

    // warp-private staging map
    unsigned* Aw = Apriv + wid * 2 * 1152;
    const int plrow = lane >> 3;                  // local row base (adds i*4)
    const int pcol  = (lane & 7) * 4;             // word offset within 32-word band
    const int kb0   = kq * 32;                    // this warp's k-offset in each chunk
    const int fbase = kq * 4 + (lane & 3);        // flag CTA index within chunk group

#define H_LOAD8(PRE, K0) do { \
        _Pragma("unroll") \
        for (int i_ = 0; i_ < 8; i_++) \
            (PRE)[i_] = __ldcg(reinterpret_cast<const uint4*>( \
                &hsrc[(mi * 32 + plrow + i_ * 4) * H + (K0) + pcol])); \
    } while (0)

    for (int t = 0; t < 512; t++) {
        // ---- LN shadow: warp 7 reduces step t-2 partials (visible by induction) ----
        if (wid == 7 && t >= 2) {
            const int t2 = t - 2;
#pragma unroll
            for (int rr = 0; rr < (64 + NC - 1) / NC; rr++) {
                int r = cta + rr * NC;
                if (r < 64) {
                    int m = r * 512 + t2;
                    float s = 0.f, qv = 0.f;
                    for (int c = lane; c < NC; c += 32) {
                        s  += __ldcg(&g_psum[(size_t)c * 32768 + m]);
                        qv += __ldcg(&g_psqs[(size_t)c * 32768 + m]);
                    }
#pragma unroll
                    for (int o = 16; o > 0; o >>= 1) {
                        s  += __shfl_xor_sync(0xffffffffu, s, o);
                        qv += __shfl_xor_sync(0xffffffffu, qv, o);
                    }
                    if (lane == 0) { __stcg(&g_sum[m], s); __stcg(&g_sqs[m], qv); }
                }
            }
        }

        float acc[2][3][4];
#pragma unroll
        for (int mf = 0; mf < 2; mf++)
#pragma unroll
            for (int nf = 0; nf < 3; nf++)
#pragma unroll
                for (int k = 0; k < 4; k++) acc[mf][nf][k] = 0.f;

        if (t > 0) {
            const unsigned* hsrc = g_h[t & 1];
            uint4 pre[8];
            // ---- chunk 0: acquire flags, speculative load, validate ----
            unsigned fv = flag_acq(&g_arr[fbase * 32]);
            H_LOAD8(pre, kb0);
            if (!__all_sync(0xffffffffu, fv >= (unsigned)t)) {
                do { fv = flag_acq(&g_arr[fbase * 32]); }
                while (!__all_sync(0xffffffffu, fv >= (unsigned)t));
                H_LOAD8(pre, kb0);
            }
#pragma unroll
            for (int i = 0; i < 8; i++)
                *reinterpret_cast<uint4*>(&Aw[(plrow + i * 4) * 36 + pcol]) = pre[i];
            __syncwarp();

            for (int ch = 0; ch < NCH; ch++) {
                unsigned fn = 0;
                if (ch + 1 < NCH) {
                    fn = flag_acq(&g_arr[((ch + 1) * 16 + fbase) * 32]);
                    const int k0 = (ch + 1) * 128 + kb0;
                    H_LOAD8(pre, k0);
                }
                const unsigned* Ab = Aw + (ch & 1) * 1152;
#pragma unroll
                for (int k8 = 0; k8 < 4; k8++) {
                    const int kb = k8 * 8;
                    const int g8 = ch * 16 + kq * 4 + k8;     // global k8 index
                    unsigned a0[4], a1[4];
                    a0[0] = Ab[q * 36 + kb + r4];
                    a0[1] = Ab[(q + 8) * 36 + kb + r4];
                    a0[2] = Ab[q * 36 + kb + r4 + 4];
                    a0[3] = Ab[(q + 8) * 36 + kb + r4 + 4];
                    a1[0] = Ab[(q + 16) * 36 + kb + r4];
                    a1[1] = Ab[(q + 24) * 36 + kb + r4];
                    a1[2] = Ab[(q + 16) * 36 + kb + r4 + 4];
                    a1[3] = Ab[(q + 24) * 36 + kb + r4 + 4];
#pragma unroll
                    for (int nf = 0; nf < 3; nf++) {
                        uint2 bb = *reinterpret_cast<const uint2*>(&Wf[(g8 * 3 + nf) * 64 + lane * 2]);
                        unsigned bfr[2] = {bb.x, bb.y};
                        mma8(acc[0][nf], a0, bfr);
                        mma8(acc[1][nf], a1, bfr);
                    }
                }
                if (ch + 1 < NCH) {
                    if (!__all_sync(0xffffffffu, fn >= (unsigned)t)) {
                        do { fn = flag_acq(&g_arr[((ch + 1) * 16 + fbase) * 32]); }
                        while (!__all_sync(0xffffffffu, fn >= (unsigned)t));
                        const int k0 = (ch + 1) * 128 + kb0;
                        H_LOAD8(pre, k0);
                    }
                    unsigned* Bb = Aw + ((ch + 1) & 1) * 1152;
#pragma unroll
                    for (int i = 0; i < 8; i++)
                        *reinterpret_cast<uint4*>(&Bb[(plrow + i * 4) * 36 + pcol]) = pre[i];
                    __syncwarp();
                }
            }
        }
        // ---- all warps store their K-partials into their kq buffer ----
        {
            float* dst = hgS + kq * 2560;
#pragma unroll
            for (int mf = 0; mf < 2; mf++)
#pragma unroll
                for (int nf = 0; nf < 3; nf++) {
                    int row = mi * 32 + mf * 16 + q;
                    int cc = nf * 8 + 2 * r4;
                    dst[row * 40 + cc]           = acc[mf][nf][0];
                    dst[row * 40 + cc + 1]       = acc[mf][nf][1];
                    dst[(row + 8) * 40 + cc]     = acc[mf][nf][2];
                    dst[(row + 8) * 40 + cc + 1] = acc[mf][nf][3];
                }
        }
        __syncthreads();

        // ---- gate epilogue: sums 4 kq buffers in kq order ----
        unsigned* hdst = g_h[(t + 1) & 1];
#pragma unroll
        for (int it = 0; it < 2; it++) {
            int b = brow + it * 32;
            float hr = hgS[b * 40 + col]      + hgS[2560 + b * 40 + col]
                     + hgS[5120 + b * 40 + col]      + hgS[7680 + b * 40 + col];
            float hz = hgS[b * 40 + 8 + col]  + hgS[2560 + b * 40 + 8 + col]
                     + hgS[5120 + b * 40 + 8 + col]  + hgS[7680 + b * 40 + 8 + col];
            float hn = hgS[b * 40 + 16 + col] + hgS[2560 + b * 40 + 16 + col]
                     + hgS[5120 + b * 40 + 16 + col] + hgS[7680 + b * 40 + 16 + col];
            float r = 1.f / (1.f + __expf(-(pxr[it] + hr)));
            float z = 1.f / (1.f + __expf(-(pxz[it] + hz)));
            float n = tanhf(pxn[it] + r * hn);
            float h2 = (1.f - z) * n + z * hl[it];
            hl[it] = h2;
            size_t m = (size_t)b * 512 + t;
            y[m * (size_t)H + c0 + col] = h2;
            __stcg(&hdst[b * H + c0 + col], f2tf(h2));
            float s = h2, qq = h2 * h2;
#pragma unroll
            for (int o = 4; o > 0; o >>= 1) {
                s  += __shfl_down_sync(0xffffffffu, s, o, 8);
                qq += __shfl_down_sync(0xffffffffu, qq, o, 8);
            }
            if (col == 0) {
                __stcg(&g_psum[(size_t)cta * 32768 + m], s);
                __stcg(&g_psqs[(size_t)cta * 32768 + m], qq);
            }
        }

        if (t < 511) {
            PF_XG(t + 1);                  // independent of h
            __syncthreads();               // h + psum stores complete CTA-wide
            if (tid == 0)
                asm volatile("st.release.gpu.u32 [%0], %1;"
                             :: "l"(&g_arr[cta * 32]), "r"((unsigned)(t + 1)) : "memory");
        }
    }
#undef PF_XG
#undef H_LOAD8
}

// ---------------- final LayerNorm (H=128, eps=0) ----------------
template<int H>
__global__ void __launch_bounds__(128) ln_k(const float* __restrict__ gw,
                                            const float* __restrict__ bw,
                                            float* __restrict__ outp) {
    constexpr int PER = H / 128;
    __shared__ float red[8];
    const int row = blockIdx.x, tid = threadIdx.x;
    const float* p = g_actB + (size_t)row * H;
    float v[PER];
    float s = 0.f;
#pragma unroll
    for (int i = 0; i < PER; i++) { v[i] = p[tid + i * 128]; s += v[i]; }
#pragma unroll
    for (int o = 16; o > 0; o >>= 1) s += __shfl_xor_sync(0xffffffffu, s, o);
    if ((tid & 31) == 0) red[tid >> 5] = s;
    __syncthreads();
    float mean = (red[0] + red[1] + red[2] + red[3]) * (1.f / H);
    float s2 = 0.f;
#pragma unroll
    for (int i = 0; i < PER; i++) { float d = v[i] - mean; s2 += d * d; }
#pragma unroll
    for (int o = 16; o > 0; o >>= 1) s2 += __shfl_xor_sync(0xffffffffu, s2, o);
    if ((tid & 31) == 0) red[4 + (tid >> 5)] = s2;
    __syncthreads();
    float var = (red[4] + red[5] + red[6] + red[7]) * (1.f / H);
    float inv = rsqrtf(var);
#pragma unroll
    for (int i = 0; i < PER; i++) {
        int c = tid + i * 128;
        outp[(size_t)row * H + c] = (v[i] - mean) * inv * gw[c] + bw[c];
    }
}

// ---------------- driver ----------------
template<int H>
static void launch_rec(const float* Whh) {
    constexpr int SM = sizeof(unsigned) * ((H / 8) * 192 + 8 * 2 * 1152)
                     + sizeof(float) * (4 * 64 * 40);
    cudaFuncSetAttribute(gru_rec<H>, cudaFuncAttributeMaxDynamicSharedMemorySize, SM);
    gru_rec<H><<<H / 8, 256, SM>>>(Whh);
}

extern "C" void kernel_launch(void* const* d_in, const int* in_sizes, int n_in,
                              void* d_out, int out_size) {
    (void)in_sizes; (void)n_in; (void)out_size;
    const float* x = (const float*)d_in[0];
    const float* Wih[6]; const float* Whh[6]; const float* gw[6]; const float* bw[6];
    for (int l = 0; l < 6; l++) {
        Wih[l] = (const float*)d_in[1 + 4 * l];
        Whh[l] = (const float*)d_in[2 + 4 * l];
        gw[l]  = (const float*)d_in[3 + 4 * l];
        bw[l]  = (const float*)d_in[4 + 4 * l];
    }
    float* actB;
    cudaGetSymbolAddress((void**)&actB, g_actB);

    static const int DIN[6] = {128, 256, 512, 1024, 512, 256};
    static const int HH[6]  = {256, 512, 1024, 512, 256, 128};

    for (int l = 0; l < 6; l++) {
        const int K = DIN[l], H = HH[l], N = 3 * H;
        const float* A = (l == 0) ? x : (const float*)actB;
        const float* gma = (l == 0) ? nullptr : gw[l - 1];
        const float* bta = (l == 0) ? nullptr : bw[l - 1];
        const int nprev = (l == 0) ? 0 : HH[l - 1] / 8;
        dim3 grid(N / 64, 256);
        if (l == 0) {
            gemm_xg<128, false><<<grid, 256>>>(A, Wih[l], N, gma, bta, nprev);
        } else {
            switch (K) {
                case 256:  gemm_xg<256, true><<<grid, 256>>>(A, Wih[l], N, gma, bta, nprev); break;
                case 512:  gemm_xg<512, true><<<grid, 256>>>(A, Wih[l], N, gma, bta, nprev); break;
                case 1024: gemm_xg<1024, true><<<grid, 256>>>(A, Wih[l], N, gma, bta, nprev); break;
            }
        }
        switch (H) {
            case 128:  launch_rec<128>(Whh[l]); break;
            case 256:  launch_rec<256>(Whh[l]); break;
            case 512:  launch_rec<512>(Whh[l]); break;
            case 1024: launch_rec<1024>(Whh[l]); break;
        }
    }
    ln_k<128><<<32768, 128>>>(gw[5], bw[5], (float*)d_out);
}

// round 12
// speedup vs baseline: 1.1070x; 1.1070x over previous
#include <cuda_runtime.h>
#include <cstdint>

// ---------------- static scratch (no allocs allowed) ----------------
__device__ float g_xg[32768 * 3072];        // input-projection buffer (max 3H=3072)
__device__ float g_actB[32768 * 1024];      // raw GRU outputs (pre-LN)
__device__ unsigned g_h[2][64 * 1024];      // double-buffered hidden state (tf32 bits)
__device__ float g_psum[128 * 32768];       // per-CTA partial row sums
__device__ float g_psqs[128 * 32768];       // per-CTA partial row sumsq
__device__ float g_sum[32768];              // reduced row sums
__device__ float g_sqs[32768];              // reduced row sumsq
__device__ unsigned g_arr[128 * 32];        // decentralized barrier slots (128B stride)

// ---------------- helpers ----------------
__device__ __forceinline__ unsigned f2tf(float x) {
    unsigned r; asm("cvt.rna.tf32.f32 %0, %1;" : "=r"(r) : "f"(x)); return r;
}
__device__ __forceinline__ void mma8(float* c, const unsigned* a, const unsigned* b) {
    asm volatile("mma.sync.aligned.m16n8k8.row.col.f32.tf32.tf32.f32 "
                 "{%0,%1,%2,%3}, {%4,%5,%6,%7}, {%8,%9}, {%0,%1,%2,%3};"
                 : "+f"(c[0]), "+f"(c[1]), "+f"(c[2]), "+f"(c[3])
                 : "r"(a[0]), "r"(a[1]), "r"(a[2]), "r"(a[3]),
                   "r"(b[0]), "r"(b[1]));
}
__device__ __forceinline__ float fast_sigmoid(float x) {
    return __fdividef(1.f, 1.f + __expf(-x));
}
__device__ __forceinline__ float fast_tanh(float x) {
    // tanh(x) = 1 - 2/(e^{2x}+1); saturates correctly for |x| large.
    return 1.f - __fdividef(2.f, __expf(2.f * x) + 1.f);
}

// ---------------- input-projection GEMM (128x128 tiles) with optional fused LN ----
// C[m,n] = sum_k LN(A[m,k]) * W[n,k];  A: [32768,K], W: [N,K], C -> g_xg [32768,N]
template<int K, bool LN>
__global__ void __launch_bounds__(256) gemm_xg(const float* __restrict__ A,
                                               const float* __restrict__ W,
                                               int N,
                                               const float* __restrict__ gma,
                                               const float* __restrict__ bta,
                                               int nprev) {
    __shared__ unsigned As[128 * 36];
    __shared__ unsigned Bs[128 * 36];
    __shared__ float gS[K], bS[K];
    __shared__ float rmS[128], rsS[128];

    const int m0 = blockIdx.y * 128;
    const int n0 = blockIdx.x * 128;
    const int tid = threadIdx.x;
    const int lane = tid & 31, wid = tid >> 5;
    const int wm = (wid & 3) * 32, wn = (wid >> 2) * 64;

    if (blockIdx.x == 0 && blockIdx.y == 0 && tid < 128)
        g_arr[tid * 32] = 0u;              // reset barrier slots for the next rec

    if (LN) {
        for (int i = tid; i < K; i += 256) { gS[i] = gma[i]; bS[i] = bta[i]; }
        if (tid < 128) {
            int m = m0 + tid;
            float s, q;
            if ((m & 511) >= 510) {
                s = 0.f; q = 0.f;
                for (int c = 0; c < nprev; c++) {
                    s += g_psum[(size_t)c * 32768 + m];
                    q += g_psqs[(size_t)c * 32768 + m];
                }
            } else {
                s = g_sum[m]; q = g_sqs[m];
            }
            float mean = s * (1.f / K);
            float var = q * (1.f / K) - mean * mean;
            rmS[tid] = mean;
            rsS[tid] = rsqrtf(var);
        }
        __syncthreads();
    }

    float acc[2][8][4];
#pragma unroll
    for (int i = 0; i < 2; i++)
#pragma unroll
        for (int j = 0; j < 8; j++)
#pragma unroll
            for (int k = 0; k < 4; k++) acc[i][j][k] = 0.f;

    const int lr = tid >> 3;
    const int lc = (tid & 7) * 4;

    for (int kc = 0; kc < K; kc += 32) {
#pragma unroll
        for (int i = 0; i < 4; i++) {
            int r = lr + i * 32;
            float4 v = *reinterpret_cast<const float4*>(&A[(size_t)(m0 + r) * K + kc + lc]);
            if (LN) {
                float mm = rmS[r], ss = rsS[r];
                int k = kc + lc;
                v.x = (v.x - mm) * ss * gS[k]     + bS[k];
                v.y = (v.y - mm) * ss * gS[k + 1] + bS[k + 1];
                v.z = (v.z - mm) * ss * gS[k + 2] + bS[k + 2];
                v.w = (v.w - mm) * ss * gS[k + 3] + bS[k + 3];
            }
            *reinterpret_cast<uint4*>(&As[r * 36 + lc]) =
                make_uint4(f2tf(v.x), f2tf(v.y), f2tf(v.z), f2tf(v.w));
        }
#pragma unroll
        for (int i = 0; i < 4; i++) {
            int r = lr + i * 32;
            float4 v = *reinterpret_cast<const float4*>(&W[(size_t)(n0 + r) * K + kc + lc]);
            *reinterpret_cast<uint4*>(&Bs[r * 36 + lc]) =
                make_uint4(f2tf(v.x), f2tf(v.y), f2tf(v.z), f2tf(v.w));
        }
        __syncthreads();
#pragma unroll
        for (int k8 = 0; k8 < 4; k8++) {
            const int kb = k8 * 8;
            unsigned a[2][4], b[8][2];
#pragma unroll
            for (int mf = 0; mf < 2; mf++) {
                int rb = wm + mf * 16 + (lane >> 2);
                a[mf][0] = As[rb * 36 + kb + (lane & 3)];
                a[mf][1] = As[(rb + 8) * 36 + kb + (lane & 3)];
                a[mf][2] = As[rb * 36 + kb + (lane & 3) + 4];
                a[mf][3] = As[(rb + 8) * 36 + kb + (lane & 3) + 4];
            }
#pragma unroll
            for (int nf = 0; nf < 8; nf++) {
                int cb = wn + nf * 8 + (lane >> 2);
                b[nf][0] = Bs[cb * 36 + kb + (lane & 3)];
                b[nf][1] = Bs[cb * 36 + kb + (lane & 3) + 4];
            }
#pragma unroll
            for (int mf = 0; mf < 2; mf++)
#pragma unroll
                for (int nf = 0; nf < 8; nf++)
                    mma8(acc[mf][nf], a[mf], b[nf]);
        }
        __syncthreads();
    }
#pragma unroll
    for (int mf = 0; mf < 2; mf++)
#pragma unroll
        for (int nf = 0; nf < 8; nf++) {
            int row = m0 + wm + mf * 16 + (lane >> 2);
            int col = n0 + wn + nf * 8 + 2 * (lane & 3);
            g_xg[(size_t)row * N + col]     = acc[mf][nf][0];
            g_xg[(size_t)row * N + col + 1] = acc[mf][nf][1];
            g_xg[(size_t)(row + 8) * N + col]     = acc[mf][nf][2];
            g_xg[(size_t)(row + 8) * N + col + 1] = acc[mf][nf][3];
        }
}

// ---------------- persistent GRU recurrence (round-10 structure) ----------------
// grid = H/8 CTAs, 256 threads, 8 warps: warp (mi = wid&1, kq = wid>>1).
// Warp-private double-buffered A staging (no block syncs in mainloop). Partials
// in 4 per-kq hgS buffers; one block sync; epilogue sums in kq order. g_h
// double-buffered. Decentralized barrier + shadow LN reduction during the spin.
template<int H>
__global__ void __launch_bounds__(256, 1) gru_rec(const float* __restrict__ Whh) {
    constexpr int NCH = H / 128;         // 128-wide global chunks (kq covers 32 each)
    constexpr int NC  = H / 8;           // == gridDim.x  (<= 128)
    extern __shared__ unsigned char smem_raw[];
    unsigned* Wf = reinterpret_cast<unsigned*>(smem_raw);      // [H/8][3][64] packed B
    unsigned* Apriv = Wf + (H / 8) * 192;                      // 8 warps x 2 x [32][36]
    float* hgS = reinterpret_cast<float*>(Apriv + 8 * 2 * 1152); // 4 x [64][40]

    const float* xg = g_xg;
    float* y = g_actB;
    const int tid = threadIdx.x;
    const int lane = tid & 31, wid = tid >> 5;
    const int cta = blockIdx.x;
    const int c0 = cta * 8;
    const int q = lane >> 2, r4 = lane & 3;
    const int mi = wid & 1;              // m-half: rows mi*32..mi*32+31
    const int kq = wid >> 1;             // k-quarter within each 128-chunk

    // one-time: Whh slice -> SMEM in fragment-packed tf32 order
    {
        constexpr int nf4 = H / 4;
        for (int idx = tid; idx < 24 * nf4; idx += 256) {
            int nn = idx / nf4;               // 0..23 : gate*8 + j
            int c4 = (idx % nf4) * 4;         // k, multiple of 4
            int gate = nn >> 3, j = nn & 7;
            float4 v = *reinterpret_cast<const float4*>(&Whh[(size_t)(gate * H + c0 + j) * H + c4]);
            int kb8 = c4 >> 3;
            int half = (c4 >> 2) & 1;
            unsigned* base = Wf + (kb8 * 3 + gate) * 64 + j * 8 + half;
            base[0] = f2tf(v.x); base[2] = f2tf(v.y);
            base[4] = f2tf(v.z); base[6] = f2tf(v.w);
        }
    }
    __syncthreads();

    const int col = tid & 7;             // epilogue: own column
    const int brow = tid >> 3;           // epilogue: batch rows brow, brow+32
    float hl[2] = {0.f, 0.f};
    float pxr[2], pxz[2], pxn[2];

#define PF_XG(TT) do { \
        _Pragma("unroll") \
        for (int it = 0; it < 2; it++) { \
            int b_ = brow + it * 32; \
            const float* xrow = xg + ((size_t)b_ * 512 + (TT)) * (size_t)(3 * H); \
            pxr[it] = __ldcs(xrow + c0 + col); \
            pxz[it] = __ldcs(xrow + H + c0 + col); \
            pxn[it] = __ldcs(xrow + 2 * H + c0 + col); \
        } } while (0)

    PF_XG(0);

    // warp-private staging map: lane covers rows (lane>>3)+i*4 (local), cols (lane&7)*4
    unsigned* Aw = Apriv + wid * 2 * 1152;
    const int plrow = lane >> 3;                  // local row base (adds i*4)
    const int pcol  = (lane & 7) * 4;             // word offset within 32-word band
    const int kb0   = kq * 32;                    // this warp's k-offset in each chunk

    for (int t = 0; t < 512; t++) {
        float acc[2][3][4];
#pragma unroll
        for (int mf = 0; mf < 2; mf++)
#pragma unroll
            for (int nf = 0; nf < 3; nf++)
#pragma unroll
                for (int k = 0; k < 4; k++) acc[mf][nf][k] = 0.f;

        if (t > 0) {
            const unsigned* hsrc = g_h[t & 1];
            uint4 pre[8];
#pragma unroll
            for (int i = 0; i < 8; i++)
                pre[i] = __ldcg(reinterpret_cast<const uint4*>(
                    &hsrc[(mi * 32 + plrow + i * 4) * H + kb0 + pcol]));
#pragma unroll
            for (int i = 0; i < 8; i++)
                *reinterpret_cast<uint4*>(&Aw[(plrow + i * 4) * 36 + pcol]) = pre[i];
            __syncwarp();

            for (int ch = 0; ch < NCH; ch++) {
                if (ch + 1 < NCH) {
                    const int k0 = (ch + 1) * 128 + kb0;
#pragma unroll
                    for (int i = 0; i < 8; i++)
                        pre[i] = __ldcg(reinterpret_cast<const uint4*>(
                            &hsrc[(mi * 32 + plrow + i * 4) * H + k0 + pcol]));
                }
                const unsigned* Ab = Aw + (ch & 1) * 1152;
#pragma unroll
                for (int k8 = 0; k8 < 4; k8++) {
                    const int kb = k8 * 8;
                    const int g8 = ch * 16 + kq * 4 + k8;     // global k8 index
                    unsigned a0[4], a1[4];
                    a0[0] = Ab[q * 36 + kb + r4];
                    a0[1] = Ab[(q + 8) * 36 + kb + r4];
                    a0[2] = Ab[q * 36 + kb + r4 + 4];
                    a0[3] = Ab[(q + 8) * 36 + kb + r4 + 4];
                    a1[0] = Ab[(q + 16) * 36 + kb + r4];
                    a1[1] = Ab[(q + 24) * 36 + kb + r4];
                    a1[2] = Ab[(q + 16) * 36 + kb + r4 + 4];
                    a1[3] = Ab[(q + 24) * 36 + kb + r4 + 4];
#pragma unroll
                    for (int nf = 0; nf < 3; nf++) {
                        uint2 bb = *reinterpret_cast<const uint2*>(&Wf[(g8 * 3 + nf) * 64 + lane * 2]);
                        unsigned bfr[2] = {bb.x, bb.y};
                        mma8(acc[0][nf], a0, bfr);
                        mma8(acc[1][nf], a1, bfr);
                    }
                }
                if (ch + 1 < NCH) {
                    unsigned* Bb = Aw + ((ch + 1) & 1) * 1152;
#pragma unroll
                    for (int i = 0; i < 8; i++)
                        *reinterpret_cast<uint4*>(&Bb[(plrow + i * 4) * 36 + pcol]) = pre[i];
                    __syncwarp();
                }
            }
        }
        // ---- all warps store their K-partials into their kq buffer ----
        {
            float* dst = hgS + kq * 2560;
#pragma unroll
            for (int mf = 0; mf < 2; mf++)
#pragma unroll
                for (int nf = 0; nf < 3; nf++) {
                    int row = mi * 32 + mf * 16 + q;
                    int cc = nf * 8 + 2 * r4;
                    dst[row * 40 + cc]           = acc[mf][nf][0];
                    dst[row * 40 + cc + 1]       = acc[mf][nf][1];
                    dst[(row + 8) * 40 + cc]     = acc[mf][nf][2];
                    dst[(row + 8) * 40 + cc + 1] = acc[mf][nf][3];
                }
        }
        __syncthreads();

        // ---- gate epilogue: sums 4 kq buffers in kq order ----
        unsigned* hdst = g_h[(t + 1) & 1];
#pragma unroll
        for (int it = 0; it < 2; it++) {
            int b = brow + it * 32;
            float hr = hgS[b * 40 + col]      + hgS[2560 + b * 40 + col]
                     + hgS[5120 + b * 40 + col]      + hgS[7680 + b * 40 + col];
            float hz = hgS[b * 40 + 8 + col]  + hgS[2560 + b * 40 + 8 + col]
                     + hgS[5120 + b * 40 + 8 + col]  + hgS[7680 + b * 40 + 8 + col];
            float hn = hgS[b * 40 + 16 + col] + hgS[2560 + b * 40 + 16 + col]
                     + hgS[5120 + b * 40 + 16 + col] + hgS[7680 + b * 40 + 16 + col];
            float r = fast_sigmoid(pxr[it] + hr);
            float z = fast_sigmoid(pxz[it] + hz);
            float n = fast_tanh(pxn[it] + r * hn);
            float h2 = (1.f - z) * n + z * hl[it];
            hl[it] = h2;
            size_t m = (size_t)b * 512 + t;
            y[m * (size_t)H + c0 + col] = h2;
            __stcg(&hdst[b * H + c0 + col], f2tf(h2));
            float s = h2, qq = h2 * h2;
#pragma unroll
            for (int o = 4; o > 0; o >>= 1) {
                s  += __shfl_down_sync(0xffffffffu, s, o, 8);
                qq += __shfl_down_sync(0xffffffffu, qq, o, 8);
            }
            if (col == 0) {
                __stcg(&g_psum[(size_t)cta * 32768 + m], s);
                __stcg(&g_psqs[(size_t)cta * 32768 + m], qq);
            }
        }

        if (t < 511) {
            PF_XG(t + 1);                  // independent of h; hides under barrier
            __syncthreads();               // h stores + hgS reads complete
            if (tid == 0)
                asm volatile("st.release.gpu.u32 [%0], %1;"
                             :: "l"(&g_arr[cta * 32]), "r"((unsigned)(t + 1)) : "memory");
            if (tid < NC) {
                unsigned v;
                do {
                    asm volatile("ld.acquire.gpu.u32 %0, [%1];"
                                 : "=r"(v) : "l"(&g_arr[tid * 32]) : "memory");
                } while (v < (unsigned)(t + 1));
            } else if (wid >= 4 && t >= 1) {
                // shadow: reduce LN partials of step t-1 while pollers spin
                int r = cta + (wid - 4) * NC;
                if (r < 64) {
                    int m = r * 512 + (t - 1);
                    float s = 0.f, qv = 0.f;
                    for (int c = lane; c < NC; c += 32) {
                        s  += __ldcg(&g_psum[(size_t)c * 32768 + m]);
                        qv += __ldcg(&g_psqs[(size_t)c * 32768 + m]);
                    }
#pragma unroll
                    for (int o = 16; o > 0; o >>= 1) {
                        s  += __shfl_xor_sync(0xffffffffu, s, o);
                        qv += __shfl_xor_sync(0xffffffffu, qv, o);
                    }
                    if (lane == 0) { __stcg(&g_sum[m], s); __stcg(&g_sqs[m], qv); }
                }
            }
            __syncthreads();
        }
    }
#undef PF_XG
}

// ---------------- final LayerNorm (H=128, eps=0) ----------------
template<int H>
__global__ void __launch_bounds__(128) ln_k(const float* __restrict__ gw,
                                            const float* __restrict__ bw,
                                            float* __restrict__ outp) {
    constexpr int PER = H / 128;
    __shared__ float red[8];
    const int row = blockIdx.x, tid = threadIdx.x;
    const float* p = g_actB + (size_t)row * H;
    float v[PER];
    float s = 0.f;
#pragma unroll
    for (int i = 0; i < PER; i++) { v[i] = p[tid + i * 128]; s += v[i]; }
#pragma unroll
    for (int o = 16; o > 0; o >>= 1) s += __shfl_xor_sync(0xffffffffu, s, o);
    if ((tid & 31) == 0) red[tid >> 5] = s;
    __syncthreads();
    float mean = (red[0] + red[1] + red[2] + red[3]) * (1.f / H);
    float s2 = 0.f;
#pragma unroll
    for (int i = 0; i < PER; i++) { float d = v[i] - mean; s2 += d * d; }
#pragma unroll
    for (int o = 16; o > 0; o >>= 1) s2 += __shfl_xor_sync(0xffffffffu, s2, o);
    if ((tid & 31) == 0) red[4 + (tid >> 5)] = s2;
    __syncthreads();
    float var = (red[4] + red[5] + red[6] + red[7]) * (1.f / H);
    float inv = rsqrtf(var);
#pragma unroll
    for (int i = 0; i < PER; i++) {
        int c = tid + i * 128;
        outp[(size_t)row * H + c] = (v[i] - mean) * inv * gw[c] + bw[c];
    }
}

// ---------------- driver ----------------
template<int H>
static void launch_rec(const float* Whh) {
    constexpr int SM = sizeof(unsigned) * ((H / 8) * 192 + 8 * 2 * 1152)
                     + sizeof(float) * (4 * 64 * 40);
    cudaFuncSetAttribute(gru_rec<H>, cudaFuncAttributeMaxDynamicSharedMemorySize, SM);
    gru_rec<H><<<H / 8, 256, SM>>>(Whh);
}

extern "C" void kernel_launch(void* const* d_in, const int* in_sizes, int n_in,
                              void* d_out, int out_size) {
    (void)in_sizes; (void)n_in; (void)out_size;
    const float* x = (const float*)d_in[0];
    const float* Wih[6]; const float* Whh[6]; const float* gw[6]; const float* bw[6];
    for (int l = 0; l < 6; l++) {
        Wih[l] = (const float*)d_in[1 + 4 * l];
        Whh[l] = (const float*)d_in[2 + 4 * l];
        gw[l]  = (const float*)d_in[3 + 4 * l];
        bw[l]  = (const float*)d_in[4 + 4 * l];
    }
    float* actB;
    cudaGetSymbolAddress((void**)&actB, g_actB);

    static const int DIN[6] = {128, 256, 512, 1024, 512, 256};
    static const int HH[6]  = {256, 512, 1024, 512, 256, 128};

    for (int l = 0; l < 6; l++) {
        const int K = DIN[l], H = HH[l], N = 3 * H;
        const float* A = (l == 0) ? x : (const float*)actB;
        const float* gma = (l == 0) ? nullptr : gw[l - 1];
        const float* bta = (l == 0) ? nullptr : bw[l - 1];
        const int nprev = (l == 0) ? 0 : HH[l - 1] / 8;
        dim3 grid(N / 128, 256);
        if (l == 0) {
            gemm_xg<128, false><<<grid, 256>>>(A, Wih[l], N, gma, bta, nprev);
        } else {
            switch (K) {
                case 256:  gemm_xg<256, true><<<grid, 256>>>(A, Wih[l], N, gma, bta, nprev); break;
                case 512:  gemm_xg<512, true><<<grid, 256>>>(A, Wih[l], N, gma, bta, nprev); break;
                case 1024: gemm_xg<1024, true><<<grid, 256>>>(A, Wih[l], N, gma, bta, nprev); break;
            }
        }
        switch (H) {
            case 128:  launch_rec<128>(Whh[l]); break;
            case 256:  launch_rec<256>(Whh[l]); break;
            case 512:  launch_rec<512>(Whh[l]); break;
            case 1024: launch_rec<1024>(Whh[l]); break;
        }
    }
    ln_k<128><<<32768, 128>>>(gw[5], bw[5], (float*)d_out);
}

// round 13
// speedup vs baseline: 1.2850x; 1.1608x over previous
#include <cuda_runtime.h>
#include <cstdint>

// ---------------- static scratch (no allocs allowed) ----------------
__device__ float g_xg[32768 * 3072];        // input-projection buffer (max 3H=3072)
__device__ float g_actB[32768 * 1024];      // raw GRU outputs (pre-LN)
__device__ unsigned g_h[2][64 * 1024];      // double-buffered hidden state (tf32 bits)
__device__ float g_psum[128 * 32768];       // per-CTA partial row sums
__device__ float g_psqs[128 * 32768];       // per-CTA partial row sumsq
__device__ float g_sum[32768];              // reduced row sums
__device__ float g_sqs[32768];              // reduced row sumsq
__device__ unsigned g_arr[128 * 32];        // decentralized barrier slots (128B stride)

// ---------------- helpers ----------------
__device__ __forceinline__ unsigned f2tf(float x) {
    unsigned r; asm("cvt.rna.tf32.f32 %0, %1;" : "=r"(r) : "f"(x)); return r;
}
__device__ __forceinline__ void mma8(float* c, const unsigned* a, const unsigned* b) {
    asm volatile("mma.sync.aligned.m16n8k8.row.col.f32.tf32.tf32.f32 "
                 "{%0,%1,%2,%3}, {%4,%5,%6,%7}, {%8,%9}, {%0,%1,%2,%3};"
                 : "+f"(c[0]), "+f"(c[1]), "+f"(c[2]), "+f"(c[3])
                 : "r"(a[0]), "r"(a[1]), "r"(a[2]), "r"(a[3]),
                   "r"(b[0]), "r"(b[1]));
}
__device__ __forceinline__ float fast_sigmoid(float x) {
    return __fdividef(1.f, 1.f + __expf(-x));
}
__device__ __forceinline__ float fast_tanh(float x) {
    return 1.f - __fdividef(2.f, __expf(2.f * x) + 1.f);
}
__device__ __forceinline__ void cpa16(unsigned* smem_dst, const void* gsrc) {
    unsigned d = (unsigned)__cvta_generic_to_shared(smem_dst);
    asm volatile("cp.async.cg.shared.global [%0], [%1], 16;" :: "r"(d), "l"(gsrc));
}
#define CP_COMMIT() asm volatile("cp.async.commit_group;" ::: "memory")
template<int N> __device__ __forceinline__ void cp_wait() {
    asm volatile("cp.async.wait_group %0;" :: "n"(N) : "memory");
}

// ---------------- input-projection GEMM (128x128 tiles) with optional fused LN ----
template<int K, bool LN>
__global__ void __launch_bounds__(256) gemm_xg(const float* __restrict__ A,
                                               const float* __restrict__ W,
                                               int N,
                                               const float* __restrict__ gma,
                                               const float* __restrict__ bta,
                                               int nprev) {
    __shared__ unsigned As[128 * 36];
    __shared__ unsigned Bs[128 * 36];
    __shared__ float gS[K], bS[K];
    __shared__ float rmS[128], rsS[128];

    const int m0 = blockIdx.y * 128;
    const int n0 = blockIdx.x * 128;
    const int tid = threadIdx.x;
    const int lane = tid & 31, wid = tid >> 5;
    const int wm = (wid & 3) * 32, wn = (wid >> 2) * 64;

    if (blockIdx.x == 0 && blockIdx.y == 0 && tid < 128)
        g_arr[tid * 32] = 0u;              // reset barrier slots for the next rec

    if (LN) {
        for (int i = tid; i < K; i += 256) { gS[i] = gma[i]; bS[i] = bta[i]; }
        if (tid < 128) {
            int m = m0 + tid;
            float s, q;
            if ((m & 511) >= 510) {
                s = 0.f; q = 0.f;
                for (int c = 0; c < nprev; c++) {
                    s += g_psum[(size_t)c * 32768 + m];
                    q += g_psqs[(size_t)c * 32768 + m];
                }
            } else {
                s = g_sum[m]; q = g_sqs[m];
            }
            float mean = s * (1.f / K);
            float var = q * (1.f / K) - mean * mean;
            rmS[tid] = mean;
            rsS[tid] = rsqrtf(var);
        }
        __syncthreads();
    }

    float acc[2][8][4];
#pragma unroll
    for (int i = 0; i < 2; i++)
#pragma unroll
        for (int j = 0; j < 8; j++)
#pragma unroll
            for (int k = 0; k < 4; k++) acc[i][j][k] = 0.f;

    const int lr = tid >> 3;
    const int lc = (tid & 7) * 4;

    for (int kc = 0; kc < K; kc += 32) {
#pragma unroll
        for (int i = 0; i < 4; i++) {
            int r = lr + i * 32;
            float4 v = *reinterpret_cast<const float4*>(&A[(size_t)(m0 + r) * K + kc + lc]);
            if (LN) {
                float mm = rmS[r], ss = rsS[r];
                int k = kc + lc;
                v.x = (v.x - mm) * ss * gS[k]     + bS[k];
                v.y = (v.y - mm) * ss * gS[k + 1] + bS[k + 1];
                v.z = (v.z - mm) * ss * gS[k + 2] + bS[k + 2];
                v.w = (v.w - mm) * ss * gS[k + 3] + bS[k + 3];
            }
            *reinterpret_cast<uint4*>(&As[r * 36 + lc]) =
                make_uint4(f2tf(v.x), f2tf(v.y), f2tf(v.z), f2tf(v.w));
        }
#pragma unroll
        for (int i = 0; i < 4; i++) {
            int r = lr + i * 32;
            float4 v = *reinterpret_cast<const float4*>(&W[(size_t)(n0 + r) * K + kc + lc]);
            *reinterpret_cast<uint4*>(&Bs[r * 36 + lc]) =
                make_uint4(f2tf(v.x), f2tf(v.y), f2tf(v.z), f2tf(v.w));
        }
        __syncthreads();
#pragma unroll
        for (int k8 = 0; k8 < 4; k8++) {
            const int kb = k8 * 8;
            unsigned a[2][4], b[8][2];
#pragma unroll
            for (int mf = 0; mf < 2; mf++) {
                int rb = wm + mf * 16 + (lane >> 2);
                a[mf][0] = As[rb * 36 + kb + (lane & 3)];
                a[mf][1] = As[(rb + 8) * 36 + kb + (lane & 3)];
                a[mf][2] = As[rb * 36 + kb + (lane & 3) + 4];
                a[mf][3] = As[(rb + 8) * 36 + kb + (lane & 3) + 4];
            }
#pragma unroll
            for (int nf = 0; nf < 8; nf++) {
                int cb = wn + nf * 8 + (lane >> 2);
                b[nf][0] = Bs[cb * 36 + kb + (lane & 3)];
                b[nf][1] = Bs[cb * 36 + kb + (lane & 3) + 4];
            }
#pragma unroll
            for (int mf = 0; mf < 2; mf++)
#pragma unroll
                for (int nf = 0; nf < 8; nf++)
                    mma8(acc[mf][nf], a[mf], b[nf]);
        }
        __syncthreads();
    }
#pragma unroll
    for (int mf = 0; mf < 2; mf++)
#pragma unroll
        for (int nf = 0; nf < 8; nf++) {
            int row = m0 + wm + mf * 16 + (lane >> 2);
            int col = n0 + wn + nf * 8 + 2 * (lane & 3);
            g_xg[(size_t)row * N + col]     = acc[mf][nf][0];
            g_xg[(size_t)row * N + col + 1] = acc[mf][nf][1];
            g_xg[(size_t)(row + 8) * N + col]     = acc[mf][nf][2];
            g_xg[(size_t)(row + 8) * N + col + 1] = acc[mf][nf][3];
        }
}

// ---------------- persistent GRU recurrence (cp.async D=4 pipeline) ----------------
// grid = H/8 CTAs, 256 threads, 8 warps: warp (mi = wid&1, kq = wid>>1).
// A staged via cp.async into warp-private XOR-swizzled 4KB slots, 4 deep: steady
// state keeps 3 chunks in flight -> h-load latency hidden behind 3 chunks of mma.
// hgS merge buffers ALIAS the A region (dead between mainloop-end and next prime;
// guarded by an extra block sync). mma order & kq fold order identical to round 12.
template<int H>
__global__ void __launch_bounds__(256, 1) gru_rec(const float* __restrict__ Whh) {
    constexpr int NCH = H / 128;         // 128-wide global chunks (kq covers 32 each)
    constexpr int NC  = H / 8;           // == gridDim.x  (<= 128)
    constexpr int D   = 4;               // pipeline depth (slots per warp)
    constexpr int P   = NCH < D ? NCH : D;
    extern __shared__ unsigned char smem_raw[];
    unsigned* Wf = reinterpret_cast<unsigned*>(smem_raw);      // [H/8][3][64] packed B
    unsigned* Apriv = Wf + (H / 8) * 192;                      // 8 warps x D x 1024 words
    float* hgS = reinterpret_cast<float*>(Apriv);              // ALIAS: 4 x [64][40]

    const float* xg = g_xg;
    float* y = g_actB;
    const int tid = threadIdx.x;
    const int lane = tid & 31, wid = tid >> 5;
    const int cta = blockIdx.x;
    const int c0 = cta * 8;
    const int q = lane >> 2, r4 = lane & 3;
    const int mi = wid & 1;              // m-half: rows mi*32..mi*32+31
    const int kq = wid >> 1;             // k-quarter within each 128-chunk
    const int kb0 = kq * 32;             // this warp's k-offset in each chunk

    // one-time: Whh slice -> SMEM in fragment-packed tf32 order
    {
        constexpr int nf4 = H / 4;
        for (int idx = tid; idx < 24 * nf4; idx += 256) {
            int nn = idx / nf4;               // 0..23 : gate*8 + j
            int c4 = (idx % nf4) * 4;         // k, multiple of 4
            int gate = nn >> 3, j = nn & 7;
            float4 v = *reinterpret_cast<const float4*>(&Whh[(size_t)(gate * H + c0 + j) * H + c4]);
            int kb8 = c4 >> 3;
            int half = (c4 >> 2) & 1;
            unsigned* base = Wf + (kb8 * 3 + gate) * 64 + j * 8 + half;
            base[0] = f2tf(v.x); base[2] = f2tf(v.y);
            base[4] = f2tf(v.z); base[6] = f2tf(v.w);
        }
    }
    __syncthreads();

    const int col = tid & 7;             // epilogue: own column
    const int brow = tid >> 3;           // epilogue: batch rows brow, brow+32
    float hl[2] = {0.f, 0.f};
    float pxr[2], pxz[2], pxn[2];

#define PF_XG(TT) do { \
        _Pragma("unroll") \
        for (int it = 0; it < 2; it++) { \
            int b_ = brow + it * 32; \
            const float* xrow = xg + ((size_t)b_ * 512 + (TT)) * (size_t)(3 * H); \
            pxr[it] = __ldcs(xrow + c0 + col); \
            pxz[it] = __ldcs(xrow + H + c0 + col); \
            pxn[it] = __ldcs(xrow + 2 * H + c0 + col); \
        } } while (0)

    PF_XG(0);

    unsigned* AwBase = Apriv + wid * (D * 1024);

#define ISSUE_CHUNK(CH, SLOT) do { \
        unsigned* _sl = AwBase + (SLOT) * 1024; \
        _Pragma("unroll") \
        for (int i_ = 0; i_ < 8; i_++) { \
            int task_ = lane + i_ * 32; \
            int row_ = task_ >> 3, unit_ = task_ & 7; \
            cpa16(_sl + row_ * 32 + ((unit_ ^ (row_ & 7)) << 2), \
                  &hsrc[(size_t)(mi * 32 + row_) * H + (CH) * 128 + kb0 + unit_ * 4]); \
        } \
        CP_COMMIT(); \
    } while (0)

    for (int t = 0; t < 512; t++) {
        float acc[2][3][4];
#pragma unroll
        for (int mf = 0; mf < 2; mf++)
#pragma unroll
            for (int nf = 0; nf < 3; nf++)
#pragma unroll
                for (int k = 0; k < 4; k++) acc[mf][nf][k] = 0.f;

        if (t > 0) {
            const unsigned* hsrc = g_h[t & 1];
            // prime P chunks
#pragma unroll
            for (int s = 0; s < P; s++) ISSUE_CHUNK(s, s);

            for (int ch = 0; ch < NCH; ch++) {
                const int rem = NCH - 1 - ch;
                if (rem >= P)      { cp_wait<P - 1>(); }
                else if (rem == 3) { cp_wait<3>(); }
                else if (rem == 2) { cp_wait<2>(); }
                else if (rem == 1) { cp_wait<1>(); }
                else               { cp_wait<0>(); }
                __syncwarp();
                const unsigned* Ab = AwBase + (ch % D) * 1024;
#pragma unroll
                for (int k8 = 0; k8 < 4; k8++) {
                    const int u0 = k8 * 2;
                    const int sw0 = ((u0 ^ q) << 2) + r4;
                    const int sw1 = (((u0 + 1) ^ q) << 2) + r4;
                    const int g8 = ch * 16 + kq * 4 + k8;     // global k8 index
                    unsigned a0[4], a1[4];
                    a0[0] = Ab[q * 32 + sw0];
                    a0[1] = Ab[(q + 8) * 32 + sw0];
                    a0[2] = Ab[q * 32 + sw1];
                    a0[3] = Ab[(q + 8) * 32 + sw1];
                    a1[0] = Ab[(q + 16) * 32 + sw0];
                    a1[1] = Ab[(q + 24) * 32 + sw0];
                    a1[2] = Ab[(q + 16) * 32 + sw1];
                    a1[3] = Ab[(q + 24) * 32 + sw1];
#pragma unroll
                    for (int nf = 0; nf < 3; nf++) {
                        uint2 bb = *reinterpret_cast<const uint2*>(&Wf[(g8 * 3 + nf) * 64 + lane * 2]);
                        unsigned bfr[2] = {bb.x, bb.y};
                        mma8(acc[0][nf], a0, bfr);
                        mma8(acc[1][nf], a1, bfr);
                    }
                }
                if (ch + P < NCH) ISSUE_CHUNK(ch + P, (ch + P) % D);
            }
        }
        __syncthreads();                 // A slots dead before hgS alias writes

        // ---- all warps store their K-partials into their kq buffer ----
        {
            float* dst = hgS + kq * 2560;
#pragma unroll
            for (int mf = 0; mf < 2; mf++)
#pragma unroll
                for (int nf = 0; nf < 3; nf++) {
                    int row = mi * 32 + mf * 16 + q;
                    int cc = nf * 8 + 2 * r4;
                    dst[row * 40 + cc]           = acc[mf][nf][0];
                    dst[row * 40 + cc + 1]       = acc[mf][nf][1];
                    dst[(row + 8) * 40 + cc]     = acc[mf][nf][2];
                    dst[(row + 8) * 40 + cc + 1] = acc[mf][nf][3];
                }
        }
        __syncthreads();

        // ---- gate epilogue: sums 4 kq buffers in kq order ----
        unsigned* hdst = g_h[(t + 1) & 1];
#pragma unroll
        for (int it = 0; it < 2; it++) {
            int b = brow + it * 32;
            float hr = hgS[b * 40 + col]      + hgS[2560 + b * 40 + col]
                     + hgS[5120 + b * 40 + col]      + hgS[7680 + b * 40 + col];
            float hz = hgS[b * 40 + 8 + col]  + hgS[2560 + b * 40 + 8 + col]
                     + hgS[5120 + b * 40 + 8 + col]  + hgS[7680 + b * 40 + 8 + col];
            float hn = hgS[b * 40 + 16 + col] + hgS[2560 + b * 40 + 16 + col]
                     + hgS[5120 + b * 40 + 16 + col] + hgS[7680 + b * 40 + 16 + col];
            float r = fast_sigmoid(pxr[it] + hr);
            float z = fast_sigmoid(pxz[it] + hz);
            float n = fast_tanh(pxn[it] + r * hn);
            float h2 = (1.f - z) * n + z * hl[it];
            hl[it] = h2;
            size_t m = (size_t)b * 512 + t;
            y[m * (size_t)H + c0 + col] = h2;
            __stcg(&hdst[b * H + c0 + col], f2tf(h2));
            float s = h2, qq = h2 * h2;
#pragma unroll
            for (int o = 4; o > 0; o >>= 1) {
                s  += __shfl_down_sync(0xffffffffu, s, o, 8);
                qq += __shfl_down_sync(0xffffffffu, qq, o, 8);
            }
            if (col == 0) {
                __stcg(&g_psum[(size_t)cta * 32768 + m], s);
                __stcg(&g_psqs[(size_t)cta * 32768 + m], qq);
            }
        }

        if (t < 511) {
            PF_XG(t + 1);                  // independent of h; hides under barrier
            __syncthreads();               // h stores + hgS reads complete
            if (tid == 0)
                asm volatile("st.release.gpu.u32 [%0], %1;"
                             :: "l"(&g_arr[cta * 32]), "r"((unsigned)(t + 1)) : "memory");
            if (tid < NC) {
                unsigned v;
                do {
                    asm volatile("ld.acquire.gpu.u32 %0, [%1];"
                                 : "=r"(v) : "l"(&g_arr[tid * 32]) : "memory");
                } while (v < (unsigned)(t + 1));
            } else if (wid >= 4 && t >= 1) {
                // shadow: reduce LN partials of step t-1 while pollers spin
                int r = cta + (wid - 4) * NC;
                if (r < 64) {
                    int m = r * 512 + (t - 1);
                    float s = 0.f, qv = 0.f;
                    for (int c = lane; c < NC; c += 32) {
                        s  += __ldcg(&g_psum[(size_t)c * 32768 + m]);
                        qv += __ldcg(&g_psqs[(size_t)c * 32768 + m]);
                    }
#pragma unroll
                    for (int o = 16; o > 0; o >>= 1) {
                        s  += __shfl_xor_sync(0xffffffffu, s, o);
                        qv += __shfl_xor_sync(0xffffffffu, qv, o);
                    }
                    if (lane == 0) { __stcg(&g_sum[m], s); __stcg(&g_sqs[m], qv); }
                }
            }
            __syncthreads();
        }
    }
#undef PF_XG
#undef ISSUE_CHUNK
}

// ---------------- final LayerNorm (H=128, eps=0) ----------------
template<int H>
__global__ void __launch_bounds__(128) ln_k(const float* __restrict__ gw,
                                            const float* __restrict__ bw,
                                            float* __restrict__ outp) {
    constexpr int PER = H / 128;
    __shared__ float red[8];
    const int row = blockIdx.x, tid = threadIdx.x;
    const float* p = g_actB + (size_t)row * H;
    float v[PER];
    float s = 0.f;
#pragma unroll
    for (int i = 0; i < PER; i++) { v[i] = p[tid + i * 128]; s += v[i]; }
#pragma unroll
    for (int o = 16; o > 0; o >>= 1) s += __shfl_xor_sync(0xffffffffu, s, o);
    if ((tid & 31) == 0) red[tid >> 5] = s;
    __syncthreads();
    float mean = (red[0] + red[1] + red[2] + red[3]) * (1.f / H);
    float s2 = 0.f;
#pragma unroll
    for (int i = 0; i < PER; i++) { float d = v[i] - mean; s2 += d * d; }
#pragma unroll
    for (int o = 16; o > 0; o >>= 1) s2 += __shfl_xor_sync(0xffffffffu, s2, o);
    if ((tid & 31) == 0) red[4 + (tid >> 5)] = s2;
    __syncthreads();
    float var = (red[4] + red[5] + red[6] + red[7]) * (1.f / H);
    float inv = rsqrtf(var);
#pragma unroll
    for (int i = 0; i < PER; i++) {
        int c = tid + i * 128;
        outp[(size_t)row * H + c] = (v[i] - mean) * inv * gw[c] + bw[c];
    }
}

// ---------------- driver ----------------
template<int H>
static void launch_rec(const float* Whh) {
    constexpr int SM = sizeof(unsigned) * ((H / 8) * 192 + 8 * 4 * 1024);
    cudaFuncSetAttribute(gru_rec<H>, cudaFuncAttributeMaxDynamicSharedMemorySize, SM);
    gru_rec<H><<<H / 8, 256, SM>>>(Whh);
}

extern "C" void kernel_launch(void* const* d_in, const int* in_sizes, int n_in,
                              void* d_out, int out_size) {
    (void)in_sizes; (void)n_in; (void)out_size;
    const float* x = (const float*)d_in[0];
    const float* Wih[6]; const float* Whh[6]; const float* gw[6]; const float* bw[6];
    for (int l = 0; l < 6; l++) {
        Wih[l] = (const float*)d_in[1 + 4 * l];
        Whh[l] = (const float*)d_in[2 + 4 * l];
        gw[l]  = (const float*)d_in[3 + 4 * l];
        bw[l]  = (const float*)d_in[4 + 4 * l];
    }
    float* actB;
    cudaGetSymbolAddress((void**)&actB, g_actB);

    static const int DIN[6] = {128, 256, 512, 1024, 512, 256};
    static const int HH[6]  = {256, 512, 1024, 512, 256, 128};

    for (int l = 0; l < 6; l++) {
        const int K = DIN[l], H = HH[l], N = 3 * H;
        const float* A = (l == 0) ? x : (const float*)actB;
        const float* gma = (l == 0) ? nullptr : gw[l - 1];
        const float* bta = (l == 0) ? nullptr : bw[l - 1];
        const int nprev = (l == 0) ? 0 : HH[l - 1] / 8;
        dim3 grid(N / 128, 256);
        if (l == 0) {
            gemm_xg<128, false><<<grid, 256>>>(A, Wih[l], N, gma, bta, nprev);
        } else {
            switch (K) {
                case 256:  gemm_xg<256, true><<<grid, 256>>>(A, Wih[l], N, gma, bta, nprev); break;
                case 512:  gemm_xg<512, true><<<grid, 256>>>(A, Wih[l], N, gma, bta, nprev); break;
                case 1024: gemm_xg<1024, true><<<grid, 256>>>(A, Wih[l], N, gma, bta, nprev); break;
            }
        }
        switch (H) {
            case 128:  launch_rec<128>(Whh[l]); break;
            case 256:  launch_rec<256>(Whh[l]); break;
            case 512:  launch_rec<512>(Whh[l]); break;
            case 1024: launch_rec<1024>(Whh[l]); break;
        }
    }
    ln_k<128><<<32768, 128>>>(gw[5], bw[5], (float*)d_out);
}